// round 5
// baseline (speedup 1.0000x reference)
#include <cuda_runtime.h>
#include <cstdint>

#define V    8      // output rows per thread
#define XPT  2      // output cols per thread
#define WIMG 1024
#define HIMG 1024

__constant__ float c_filt[25];

__global__ __launch_bounds__(256, 6)
void erosion5x5_kernel(const float* __restrict__ img,
                       float* __restrict__ out)
{
    const int plane = blockIdx.z;                              // fused (b,c): 0..95
    const int y0    = blockIdx.x * V;                          // output row base
    const int x0    = (blockIdx.y * 256 + threadIdx.x) * XPT;  // 0,2,...,1022

    const float* p = img + (size_t)plane * HIMG * WIMG;
    float*       q = out + (size_t)plane * HIMG * WIMG + (size_t)y0 * WIMG + x0;

    const float INF = __int_as_float(0x7f800000);

    float acc[V][XPT];
#pragma unroll
    for (int o = 0; o < V; ++o)
#pragma unroll
        for (int c = 0; c < XPT; ++c) acc[o][c] = INF;

    // Thread needs cols x0-2 .. x0+3.
    const bool leftEdge  = (x0 == 0);              // cols x0-2, x0-1 OOB
    const bool rightEdge = (x0 + 2 >= WIMG);       // cols x0+2, x0+3 OOB (only x0==1022)

    // Stream input rows y0-2 .. y0+V+1 through registers.
    // s[k] = img[row][x0 - 2 + k], k = 0..5 (three aligned float2 loads).
#pragma unroll
    for (int r = 0; r < V + 4; ++r) {
        const int yy = y0 - 2 + r;
        float s[6];
        if (yy >= 0 && yy < HIMG) {
            const float* row = p + (size_t)yy * WIMG + x0;
            float2 a, b, c2;
            a  = leftEdge  ? make_float2(INF, INF)
                           : *reinterpret_cast<const float2*>(row - 2);
            b  = *reinterpret_cast<const float2*>(row);
            c2 = rightEdge ? make_float2(INF, INF)
                           : *reinterpret_cast<const float2*>(row + 2);
            s[0] = a.x;  s[1] = a.y;
            s[2] = b.x;  s[3] = b.y;
            s[4] = c2.x; s[5] = c2.y;
        } else {
#pragma unroll
            for (int k = 0; k < 6; ++k) s[k] = INF;
        }

        // Input row (rel index r) feeds output row o = r - i through filter row i.
#pragma unroll
        for (int i = 0; i < 5; ++i) {
            const int o = r - i;
            if (o < 0 || o >= V) continue;   // compile-time pruned (r, i constants)
#pragma unroll
            for (int j = 0; j < 5; ++j) {
                const float w = c_filt[i * 5 + j];   // LDCU -> uniform reg, 0 GPRs
#pragma unroll
                for (int c = 0; c < XPT; ++c) {
                    // tap col = x0 + c + j - 2  ->  s index = c + j
                    acc[o][c] = fminf(acc[o][c], s[c + j] - w);
                }
            }
        }
    }

#pragma unroll
    for (int o = 0; o < V; ++o) {
        float2 v = make_float2(acc[o][0], acc[o][1]);
        *reinterpret_cast<float2*>(q + (size_t)o * WIMG) = v;   // STG.64
    }
}

extern "C" void kernel_launch(void* const* d_in, const int* in_sizes, int n_in,
                              void* d_out, int out_size)
{
    const float* img  = (const float*)d_in[0];
    float*       out  = (float*)d_out;

    // Filter -> constant bank (D2D memcpy node; graph-capturable, no allocation).
    cudaMemcpyToSymbolAsync(c_filt, d_in[1], 25 * sizeof(float), 0,
                            cudaMemcpyDeviceToDevice, 0);

    const int planes = in_sizes[0] / (HIMG * WIMG);   // 32*3 = 96

    dim3 block(256);
    dim3 grid(HIMG / V, WIMG / (256 * XPT), planes);  // (128, 2, 96)
    erosion5x5_kernel<<<grid, block>>>(img, out);
}

// round 6
// speedup vs baseline: 1.1906x; 1.1906x over previous
#include <cuda_runtime.h>
#include <cuda_fp16.h>
#include <cstdint>

#define V    8      // output rows per thread
#define XPT  4      // output cols per thread (two half2 pairs)
#define WIMG 1024
#define HIMG 1024

__constant__ float c_filt[25];

__global__ __launch_bounds__(256, 4)
void erosion5x5_kernel(const float* __restrict__ img,
                       float* __restrict__ out)
{
    const int plane = blockIdx.y;                 // fused (b,c): 0..95
    const int y0    = blockIdx.x * V;             // output row base
    const int x0    = threadIdx.x * XPT;          // 0, 4, ..., 1020

    const float* p = img + (size_t)plane * HIMG * WIMG;
    float*       q = out + (size_t)plane * HIMG * WIMG + (size_t)y0 * WIMG + x0;

    const float  INF  = __int_as_float(0x7f800000);
    const __half2 INF2 = __floats2half2_rn(INF, INF);

    // Filter -> packed (w,w) half2 registers, converted once per thread.
    __half2 w2[25];
#pragma unroll
    for (int t = 0; t < 25; ++t) {
        const float w = c_filt[t];
        w2[t] = __floats2half2_rn(w, w);
    }

    // Accumulators: V rows x 2 column-pairs, fp16x2.
    __half2 acc[V][2];
#pragma unroll
    for (int o = 0; o < V; ++o) { acc[o][0] = INF2; acc[o][1] = INF2; }

    // Thread needs cols x0-2 .. x0+5.
    const bool leftEdge  = (x0 == 0);              // cols x0-2, x0-1 OOB
    const bool rightEdge = (x0 + 4 >= WIMG);       // cols x0+4, x0+5 OOB (only x0==1020)

    // Stream input rows y0-2 .. y0+V+1 through registers.
    // s[k] = img[row][x0 - 2 + k], k = 0..7  (float2 + float4 + float2, all aligned).
#pragma unroll
    for (int r = 0; r < V + 4; ++r) {
        const int yy = y0 - 2 + r;
        __half2 P[7];                    // P[k] = (s[k], s[k+1]), k = 0..6
        if (yy >= 0 && yy < HIMG) {
            const float* row = p + (size_t)yy * WIMG + x0;
            float2 a  = leftEdge  ? make_float2(INF, INF)
                                  : *reinterpret_cast<const float2*>(row - 2);
            float4 b  = *reinterpret_cast<const float4*>(row);
            float2 c2 = rightEdge ? make_float2(INF, INF)
                                  : *reinterpret_cast<const float2*>(row + 4);
            // s = {a.x, a.y, b.x, b.y, b.z, b.w, c2.x, c2.y}
            P[0] = __floats2half2_rn(a.x, a.y);
            P[1] = __floats2half2_rn(a.y, b.x);
            P[2] = __floats2half2_rn(b.x, b.y);
            P[3] = __floats2half2_rn(b.y, b.z);
            P[4] = __floats2half2_rn(b.z, b.w);
            P[5] = __floats2half2_rn(b.w, c2.x);
            P[6] = __floats2half2_rn(c2.x, c2.y);
        } else {
#pragma unroll
            for (int k = 0; k < 7; ++k) P[k] = INF2;
        }

        // Input row (rel index r) feeds output row o = r - i through filter row i.
#pragma unroll
        for (int i = 0; i < 5; ++i) {
            const int o = r - i;
            if (o < 0 || o >= V) continue;   // compile-time pruned
#pragma unroll
            for (int j = 0; j < 5; ++j) {
                const __half2 w = w2[i * 5 + j];
                // cols (0,1): taps start at s[j]   -> P[j]
                // cols (2,3): taps start at s[j+2] -> P[j+2]
                acc[o][0] = __hmin2(acc[o][0], __hsub2(P[j],     w));
                acc[o][1] = __hmin2(acc[o][1], __hsub2(P[j + 2], w));
            }
        }
    }

#pragma unroll
    for (int o = 0; o < V; ++o) {
        const float2 lo = __half22float2(acc[o][0]);
        const float2 hi = __half22float2(acc[o][1]);
        float4 v = make_float4(lo.x, lo.y, hi.x, hi.y);
        *reinterpret_cast<float4*>(q + (size_t)o * WIMG) = v;   // STG.128
    }
}

extern "C" void kernel_launch(void* const* d_in, const int* in_sizes, int n_in,
                              void* d_out, int out_size)
{
    const float* img = (const float*)d_in[0];
    float*       out = (float*)d_out;

    // Filter -> constant bank (D2D memcpy node; graph-capturable, no allocation).
    cudaMemcpyToSymbolAsync(c_filt, d_in[1], 25 * sizeof(float), 0,
                            cudaMemcpyDeviceToDevice, 0);

    const int planes = in_sizes[0] / (HIMG * WIMG);   // 32*3 = 96

    dim3 block(WIMG / XPT);          // 256 threads: one row-strip of the plane
    dim3 grid(HIMG / V, planes);     // (128, 96)
    erosion5x5_kernel<<<grid, block>>>(img, out);
}

// round 7
// speedup vs baseline: 1.2569x; 1.0557x over previous
#include <cuda_runtime.h>
#include <cuda_fp16.h>
#include <cstdint>

#define V    8      // output rows per thread
#define XPT  4      // output cols per thread (two half2 pairs)
#define WIMG 1024
#define HIMG 1024

__constant__ __half2 c_w2[25];        // packed (w,w) per tap — read via LDCU, 0 GPRs
__device__   __half2 g_w2_stage[25];  // staging (device-writable scratch)

__global__ void prep_weights(const float* __restrict__ filt)
{
    const int t = threadIdx.x;
    if (t < 25) g_w2_stage[t] = __floats2half2_rn(filt[t], filt[t]);
}

__global__ __launch_bounds__(256, 6)
void erosion5x5_kernel(const float* __restrict__ img,
                       float* __restrict__ out)
{
    const int plane = blockIdx.y;                 // fused (b,c): 0..95
    const int y0    = blockIdx.x * V;             // output row base
    const int x0    = threadIdx.x * XPT;          // 0, 4, ..., 1020

    const float* p = img + (size_t)plane * HIMG * WIMG;
    float*       q = out + (size_t)plane * HIMG * WIMG + (size_t)y0 * WIMG + x0;

    const float   INF  = __int_as_float(0x7f800000);
    const __half2 INF2 = __floats2half2_rn(INF, INF);

    // Accumulators: V rows x 2 column-pairs, fp16x2.
    __half2 acc[V][2];
#pragma unroll
    for (int o = 0; o < V; ++o) { acc[o][0] = INF2; acc[o][1] = INF2; }

    // Thread needs cols x0-2 .. x0+5.
    const bool leftEdge  = (x0 == 0);              // cols x0-2, x0-1 OOB
    const bool rightEdge = (x0 + 4 >= WIMG);       // cols x0+4, x0+5 OOB (only x0==1020)

    // Stream input rows y0-2 .. y0+V+1 through registers.
    // s[k] = img[row][x0 - 2 + k], k = 0..7  (float2 + float4 + float2, all aligned).
#pragma unroll
    for (int r = 0; r < V + 4; ++r) {
        const int yy = y0 - 2 + r;
        __half2 P[7];                    // P[k] = (s[k], s[k+1]), k = 0..6
        if (yy >= 0 && yy < HIMG) {
            const float* row = p + (size_t)yy * WIMG + x0;
            float2 a  = leftEdge  ? make_float2(INF, INF)
                                  : *reinterpret_cast<const float2*>(row - 2);
            float4 b  = *reinterpret_cast<const float4*>(row);
            float2 c2 = rightEdge ? make_float2(INF, INF)
                                  : *reinterpret_cast<const float2*>(row + 4);
            // s = {a.x, a.y, b.x, b.y, b.z, b.w, c2.x, c2.y}
            P[0] = __floats2half2_rn(a.x, a.y);
            P[1] = __floats2half2_rn(a.y, b.x);
            P[2] = __floats2half2_rn(b.x, b.y);
            P[3] = __floats2half2_rn(b.y, b.z);
            P[4] = __floats2half2_rn(b.z, b.w);
            P[5] = __floats2half2_rn(b.w, c2.x);
            P[6] = __floats2half2_rn(c2.x, c2.y);
        } else {
#pragma unroll
            for (int k = 0; k < 7; ++k) P[k] = INF2;
        }

        // Input row (rel index r) feeds output row o = r - i through filter row i.
#pragma unroll
        for (int i = 0; i < 5; ++i) {
            const int o = r - i;
            if (o < 0 || o >= V) continue;   // compile-time pruned
#pragma unroll
            for (int j = 0; j < 5; ++j) {
                const __half2 w = c_w2[i * 5 + j];   // constant load, 0 GPRs
                // cols (0,1): taps start at s[j]   -> P[j]
                // cols (2,3): taps start at s[j+2] -> P[j+2]
                acc[o][0] = __hmin2(acc[o][0], __hsub2(P[j],     w));
                acc[o][1] = __hmin2(acc[o][1], __hsub2(P[j + 2], w));
            }
        }
    }

#pragma unroll
    for (int o = 0; o < V; ++o) {
        const float2 lo = __half22float2(acc[o][0]);
        const float2 hi = __half22float2(acc[o][1]);
        float4 v = make_float4(lo.x, lo.y, hi.x, hi.y);
        *reinterpret_cast<float4*>(q + (size_t)o * WIMG) = v;   // STG.128
    }
}

extern "C" void kernel_launch(void* const* d_in, const int* in_sizes, int n_in,
                              void* d_out, int out_size)
{
    const float* img  = (const float*)d_in[0];
    const float* filt = (const float*)d_in[1];
    float*       out  = (float*)d_out;

    // 1) Convert filter -> packed half2 in device staging array.
    prep_weights<<<1, 32>>>(filt);

    // 2) Stage -> constant bank (D2D memcpy node; graph-capturable, no alloc).
    void* stage_ptr = nullptr;
    cudaGetSymbolAddress(&stage_ptr, g_w2_stage);
    cudaMemcpyToSymbolAsync(c_w2, stage_ptr, 25 * sizeof(__half2), 0,
                            cudaMemcpyDeviceToDevice, 0);

    const int planes = in_sizes[0] / (HIMG * WIMG);   // 32*3 = 96

    dim3 block(WIMG / XPT);          // 256 threads: one row-strip of the plane
    dim3 grid(HIMG / V, planes);     // (128, 96)
    erosion5x5_kernel<<<grid, block>>>(img, out);
}